// round 13
// baseline (speedup 1.0000x reference)
#include <cuda_runtime.h>

#define BB 16
#define CC 1024
#define NLOC 3136            // 16*14*14
#define N4 784               // NLOC/4
#define CSPLIT 8
#define CCHUNK 128           // CC/CSPLIT
#define BLOCKS_PER_B 56      // 7 * CSPLIT
#define MARGIN 0.2f
#define INV_TEMP 1000.0f
#define SCALE 100000.0f

// Zero at module load; softmax kernel re-zeroes after consuming, so every
// replay starts clean (deterministic).
__device__ float4 g_pd[BB * N4];
__device__ float4 g_nd[BB * N4];
__device__ unsigned int g_cnt[BB];

// ---------------------------------------------------------------------------
// Kernel 1 (R8-validated loop): fused batched matvec, C split 8-ways, float4
// loads, partials folded via atomicAdd (REDG) into g_pd/g_nd.
// After posting, each block releases its batch counter (per-batch readiness).
// grid = (7, 8, 16) = 896 blocks, block = 128  — all resident in wave 1.
// ---------------------------------------------------------------------------
__global__ void __launch_bounds__(128)
dot_kernel(const float* __restrict__ ft,
           const float* __restrict__ pos,
           const float* __restrict__ neg,
           float* __restrict__ out, int out_size)
{
    __shared__ float s_pos[CCHUNK];
    __shared__ float s_neg[CCHUNK];
    const int b  = blockIdx.z;
    const int cs = blockIdx.y;
    const int c0 = cs * CCHUNK;

    if (blockIdx.x == 0 && blockIdx.y == 0 && blockIdx.z == 0 &&
        threadIdx.x == 0 && out_size > BB * NLOC)
        out[BB * NLOC] = 0.0f;

    s_pos[threadIdx.x] = pos[b * CC + c0 + threadIdx.x];
    s_neg[threadIdx.x] = neg[b * CC + c0 + threadIdx.x];
    __syncthreads();

    const int n4 = blockIdx.x * 128 + threadIdx.x;
    if (n4 < N4) {
        const float4* base = (const float4*)(ft + (size_t)b * CC * NLOC
                                                + (size_t)c0 * NLOC) + n4;
        float4 pd = {0.f, 0.f, 0.f, 0.f};
        float4 nd = {0.f, 0.f, 0.f, 0.f};

#pragma unroll 8
        for (int c = 0; c < CCHUNK; ++c) {
            float4 v = __ldg(base + (size_t)c * N4);
            float sp = s_pos[c], sn = s_neg[c];
            pd.x = fmaf(v.x, sp, pd.x);  pd.y = fmaf(v.y, sp, pd.y);
            pd.z = fmaf(v.z, sp, pd.z);  pd.w = fmaf(v.w, sp, pd.w);
            nd.x = fmaf(v.x, sn, nd.x);  nd.y = fmaf(v.y, sn, nd.y);
            nd.z = fmaf(v.z, sn, nd.z);  nd.w = fmaf(v.w, sn, nd.w);
        }

        float* dp = (float*)&g_pd[b * N4 + n4];
        float* dn = (float*)&g_nd[b * N4 + n4];
        atomicAdd(dp + 0, pd.x);  atomicAdd(dp + 1, pd.y);
        atomicAdd(dp + 2, pd.z);  atomicAdd(dp + 3, pd.w);
        atomicAdd(dn + 0, nd.x);  atomicAdd(dn + 1, nd.y);
        atomicAdd(dn + 2, nd.z);  atomicAdd(dn + 3, nd.w);
    }

    // Release: REDG results visible before counter increment.
    __threadfence();
    __syncthreads();
    if (threadIdx.x == 0)
        atomicAdd(&g_cnt[b], 1u);

    cudaTriggerProgrammaticLaunchCompletion();
}

// ---------------------------------------------------------------------------
// Kernel 2 (PDL, per-batch spin): per-batch softmax + margin loss.
// Launched with programmatic stream serialization; does NOT grid-sync.
// Block b spins until its batch's 56 dot blocks have posted, then proceeds —
// overlapping earlier batches' softmax with the dot grid's drain.
// ---------------------------------------------------------------------------
__global__ void __launch_bounds__(1024)
softmax_loss_kernel(float* __restrict__ out, int out_size)
{
    const int b   = blockIdx.x;
    const int tid = threadIdx.x;
    __shared__ float red[32];
    const bool act = tid < N4;

    // per-batch readiness spin (acquire)
    if (tid == 0) {
        while (atomicAdd(&g_cnt[b], 0u) < BLOCKS_PER_B) { }
        g_cnt[b] = 0;   // self-reset for next replay (stream-ordered)
    }
    __syncthreads();
    __threadfence();

    float4 pd = {-1e30f, -1e30f, -1e30f, -1e30f};
    float4 nd = {0.f, 0.f, 0.f, 0.f};
    const float4 z4 = {0.f, 0.f, 0.f, 0.f};
    if (act) {
        pd = g_pd[b * N4 + tid];
        nd = g_nd[b * N4 + tid];
        g_pd[b * N4 + tid] = z4;   // reset for next replay
        g_nd[b * N4 + tid] = z4;
    }

    // ---- block max ----
    float m = fmaxf(fmaxf(pd.x, pd.y), fmaxf(pd.z, pd.w));
#pragma unroll
    for (int o = 16; o > 0; o >>= 1)
        m = fmaxf(m, __shfl_xor_sync(0xffffffffu, m, o));
    if ((tid & 31) == 0) red[tid >> 5] = m;
    __syncthreads();
    if (tid < 32) {
        float v = red[tid];
#pragma unroll
        for (int o = 16; o > 0; o >>= 1)
            v = fmaxf(v, __shfl_xor_sync(0xffffffffu, v, o));
        if (tid == 0) red[0] = v;
    }
    __syncthreads();
    const float mx = red[0];
    __syncthreads();

    // ---- exp + block sum ----
    float4 e = {0.f, 0.f, 0.f, 0.f};
    if (act) {
        e.x = expf((pd.x - mx) * INV_TEMP);
        e.y = expf((pd.y - mx) * INV_TEMP);
        e.z = expf((pd.z - mx) * INV_TEMP);
        e.w = expf((pd.w - mx) * INV_TEMP);
    }
    float s = e.x + e.y + e.z + e.w;
#pragma unroll
    for (int o = 16; o > 0; o >>= 1)
        s += __shfl_xor_sync(0xffffffffu, s, o);
    if ((tid & 31) == 0) red[tid >> 5] = s;
    __syncthreads();
    if (tid < 32) {
        float v = red[tid];
#pragma unroll
        for (int o = 16; o > 0; o >>= 1)
            v += __shfl_xor_sync(0xffffffffu, v, o);
        if (tid == 0) red[0] = v;
    }
    __syncthreads();
    const float invZ = 1.0f / red[0];
    __syncthreads();

    // ---- attn write + loss partial ----
    float l = 0.0f;
    if (act) {
        float4 a;
        a.x = e.x * invZ;  a.y = e.y * invZ;
        a.z = e.z * invZ;  a.w = e.w * invZ;
        ((float4*)(out + b * NLOC))[tid] = a;
        l = fmaf(fmaxf(MARGIN + (nd.x - pd.x) * SCALE, 0.0f), a.x, l);
        l = fmaf(fmaxf(MARGIN + (nd.y - pd.y) * SCALE, 0.0f), a.y, l);
        l = fmaf(fmaxf(MARGIN + (nd.z - pd.z) * SCALE, 0.0f), a.z, l);
        l = fmaf(fmaxf(MARGIN + (nd.w - pd.w) * SCALE, 0.0f), a.w, l);
    }
#pragma unroll
    for (int o = 16; o > 0; o >>= 1)
        l += __shfl_xor_sync(0xffffffffu, l, o);
    if ((tid & 31) == 0) red[tid >> 5] = l;
    __syncthreads();
    if (tid < 32) {
        float v = red[tid];
#pragma unroll
        for (int o = 16; o > 0; o >>= 1)
            v += __shfl_xor_sync(0xffffffffu, v, o);
        if (tid == 0 && out_size > BB * NLOC)
            atomicAdd(out + BB * NLOC, v * (1.0f / (float)BB));
    }
}

extern "C" void kernel_launch(void* const* d_in, const int* in_sizes, int n_in,
                              void* d_out, int out_size)
{
    const float* ft  = (const float*)d_in[0];
    const float* pos = (const float*)d_in[1];
    const float* neg = (const float*)d_in[2];
    float* out = (float*)d_out;

    dim3 grid1(7, CSPLIT, BB);
    dot_kernel<<<grid1, 128>>>(ft, pos, neg, out, out_size);

    // PDL: softmax blocks become resident during the dot grid's drain and
    // gate themselves on per-batch counters.
    cudaLaunchConfig_t cfg = {};
    cfg.gridDim  = dim3(BB, 1, 1);
    cfg.blockDim = dim3(1024, 1, 1);
    cfg.dynamicSmemBytes = 0;
    cfg.stream = 0;
    cudaLaunchAttribute attrs[1];
    attrs[0].id = cudaLaunchAttributeProgrammaticStreamSerialization;
    attrs[0].val.programmaticStreamSerializationAllowed = 1;
    cfg.attrs = attrs;
    cfg.numAttrs = 1;
    cudaLaunchKernelEx(&cfg, softmax_loss_kernel, out, out_size);
}

// round 14
// speedup vs baseline: 1.0548x; 1.0548x over previous
#include <cuda_runtime.h>

#define BB 16
#define CC 1024
#define NLOC 3136            // 16*14*14
#define N4 784               // NLOC/4
#define CSPLIT 8
#define CCHUNK 128           // CC/CSPLIT
#define BLOCKS_PER_B 56      // 7 * CSPLIT
#define NITER 7              // ceil(N4/128)
#define MARGIN 0.2f
#define INV_TEMP 1000.0f
#define SCALE 100000.0f

// Zero at module load; epilogue blocks re-zero after consuming -> every
// replay starts clean (deterministic).
__device__ float4 g_pd[BB * N4];
__device__ float4 g_nd[BB * N4];
__device__ float  g_loss[BB];
__device__ unsigned int g_cnt[BB];
__device__ unsigned int g_cnt2;

__global__ void __launch_bounds__(128)
fused_kernel(const float* __restrict__ ft,
             const float* __restrict__ pos,
             const float* __restrict__ neg,
             float* __restrict__ out, int out_size)
{
    const int tid = threadIdx.x;

    if (blockIdx.z < BB) {
        // ================= DOT PATH (R8-identical) =================
        __shared__ float s_pos[CCHUNK];
        __shared__ float s_neg[CCHUNK];
        const int b  = blockIdx.z;
        const int cs = blockIdx.y;
        const int c0 = cs * CCHUNK;

        s_pos[tid] = pos[b * CC + c0 + tid];
        s_neg[tid] = neg[b * CC + c0 + tid];
        __syncthreads();

        const int n4 = blockIdx.x * 128 + tid;
        if (n4 < N4) {
            const float4* base = (const float4*)(ft + (size_t)b * CC * NLOC
                                                    + (size_t)c0 * NLOC) + n4;
            float4 pd = {0.f, 0.f, 0.f, 0.f};
            float4 nd = {0.f, 0.f, 0.f, 0.f};

#pragma unroll 8
            for (int c = 0; c < CCHUNK; ++c) {
                float4 v = __ldg(base + (size_t)c * N4);
                float sp = s_pos[c], sn = s_neg[c];
                pd.x = fmaf(v.x, sp, pd.x);  pd.y = fmaf(v.y, sp, pd.y);
                pd.z = fmaf(v.z, sp, pd.z);  pd.w = fmaf(v.w, sp, pd.w);
                nd.x = fmaf(v.x, sn, nd.x);  nd.y = fmaf(v.y, sn, nd.y);
                nd.z = fmaf(v.z, sn, nd.z);  nd.w = fmaf(v.w, sn, nd.w);
            }

            float* dp = (float*)&g_pd[b * N4 + n4];
            float* dn = (float*)&g_nd[b * N4 + n4];
            atomicAdd(dp + 0, pd.x);  atomicAdd(dp + 1, pd.y);
            atomicAdd(dp + 2, pd.z);  atomicAdd(dp + 3, pd.w);
            atomicAdd(dn + 0, nd.x);  atomicAdd(dn + 1, nd.y);
            atomicAdd(dn + 2, nd.z);  atomicAdd(dn + 3, nd.w);
        }

        // release: REDG results visible before counter increment
        __threadfence();
        __syncthreads();
        if (tid == 0)
            atomicAdd(&g_cnt[b], 1u);
        return;
    }

    // ================= EPILOGUE PATH (16 blocks of the z==16 slice) ========
    const int eb = blockIdx.y * 7 + blockIdx.x;   // 0..55
    if (eb >= BB) return;
    const int b = eb;

    __shared__ float red[4];
    __shared__ float red2[4];

    // wait for this batch's 56 dot blocks (all blocks co-resident: no starve)
    if (tid == 0) {
        volatile unsigned int* c = &g_cnt[b];
        while (*c < BLOCKS_PER_B) { }
        g_cnt[b] = 0;   // self-reset for next replay
    }
    __syncthreads();
    __threadfence();    // acquire

    const float4 z4 = {0.f, 0.f, 0.f, 0.f};
    float4 lpd[NITER], lnd[NITER];

    // pass 1: load rows, zero globals, block max
    float m = -1e30f;
#pragma unroll
    for (int i = 0; i < NITER; ++i) {
        int idx = tid + i * 128;
        if (idx < N4) {
            lpd[i] = g_pd[b * N4 + idx];
            lnd[i] = g_nd[b * N4 + idx];
            g_pd[b * N4 + idx] = z4;
            g_nd[b * N4 + idx] = z4;
            m = fmaxf(m, fmaxf(fmaxf(lpd[i].x, lpd[i].y),
                               fmaxf(lpd[i].z, lpd[i].w)));
        }
    }
#pragma unroll
    for (int o = 16; o > 0; o >>= 1)
        m = fmaxf(m, __shfl_xor_sync(0xffffffffu, m, o));
    if ((tid & 31) == 0) red[tid >> 5] = m;
    __syncthreads();
    const float mx = fmaxf(fmaxf(red[0], red[1]), fmaxf(red[2], red[3]));
    __syncthreads();

    // pass 2: e = exp(...), merged Z and sum(lm*e); stash e back in lpd
    float s = 0.0f, le = 0.0f;
#pragma unroll
    for (int i = 0; i < NITER; ++i) {
        int idx = tid + i * 128;
        if (idx < N4) {
            float4 pd = lpd[i], nd = lnd[i];
            float4 e;
            e.x = expf((pd.x - mx) * INV_TEMP);
            e.y = expf((pd.y - mx) * INV_TEMP);
            e.z = expf((pd.z - mx) * INV_TEMP);
            e.w = expf((pd.w - mx) * INV_TEMP);
            s += e.x + e.y + e.z + e.w;
            le = fmaf(fmaxf(MARGIN + (nd.x - pd.x) * SCALE, 0.0f), e.x, le);
            le = fmaf(fmaxf(MARGIN + (nd.y - pd.y) * SCALE, 0.0f), e.y, le);
            le = fmaf(fmaxf(MARGIN + (nd.z - pd.z) * SCALE, 0.0f), e.z, le);
            le = fmaf(fmaxf(MARGIN + (nd.w - pd.w) * SCALE, 0.0f), e.w, le);
            lpd[i] = e;
        }
    }
#pragma unroll
    for (int o = 16; o > 0; o >>= 1) {
        s  += __shfl_xor_sync(0xffffffffu, s, o);
        le += __shfl_xor_sync(0xffffffffu, le, o);
    }
    if ((tid & 31) == 0) { red[tid >> 5] = s;  red2[tid >> 5] = le; }
    __syncthreads();
    const float invZ  = 1.0f / (red[0] + red[1] + red[2] + red[3]);
    const float lossb = (red2[0] + red2[1] + red2[2] + red2[3]) * invZ;

    // pass 3: attn = e * invZ
#pragma unroll
    for (int i = 0; i < NITER; ++i) {
        int idx = tid + i * 128;
        if (idx < N4) {
            float4 e = lpd[i];
            float4 a;
            a.x = e.x * invZ;  a.y = e.y * invZ;
            a.z = e.z * invZ;  a.w = e.w * invZ;
            ((float4*)(out + b * NLOC))[idx] = a;
        }
    }

    // super-tail: last epilogue block sums the 16 losses, writes scalar
    if (tid == 0) {
        g_loss[b] = lossb;
        __threadfence();
        unsigned int old = atomicAdd(&g_cnt2, 1u);
        if (old == BB - 1) {
            g_cnt2 = 0;   // self-reset
            __threadfence();
            float tot = 0.0f;
#pragma unroll
            for (int bb = 0; bb < BB; ++bb) tot += g_loss[bb];
            if (out_size > BB * NLOC)
                out[BB * NLOC] = tot * (1.0f / (float)BB);
        }
    }
}

extern "C" void kernel_launch(void* const* d_in, const int* in_sizes, int n_in,
                              void* d_out, int out_size)
{
    const float* ft  = (const float*)d_in[0];
    const float* pos = (const float*)d_in[1];
    const float* neg = (const float*)d_in[2];
    float* out = (float*)d_out;

    dim3 grid(7, CSPLIT, BB + 1);   // z<16: dot; z==16: 16 epilogue blocks
    fused_kernel<<<grid, 128>>>(ft, pos, neg, out, out_size);
}